// round 14
// baseline (speedup 1.0000x reference)
#include <cuda_runtime.h>
#include <cuda_fp16.h>
#include <cstdint>

// ---------------- problem constants ----------------
#define NUM_EXPERTS 64
#define DIM 2048
#define HIDDEN 1024
#define TOK_PER_E 256
#define TOTAL_TOKENS (NUM_EXPERTS * TOK_PER_E)
#define NTHREADS 512

// scratch: fp16 fragment-packed x (64MB) and h (32MB)
__device__ uint4 g_xp[(size_t)TOTAL_TOKENS * DIM / 8];
__device__ uint4 g_hp[(size_t)TOTAL_TOKENS * HIDDEN / 8];

// ---------------- smem layout ----------------
// A stage: 32KB (256 rows x 64 k fp16, fragment-packed), 2-stage ring.
// B stage: 16KB, 2-stage.
#define A_PK 32768
#define B_BASE (2 * A_PK)                // 65536
#define SMEM_TOT (B_BASE + 2 * 16384)    // 98304

// ---------------- helpers ----------------
__device__ __forceinline__ uint32_t smem_u32(const void* p) {
    uint32_t a;
    asm("{ .reg .u64 t; cvta.to.shared.u64 t, %1; cvt.u32.u64 %0, t; }" : "=r"(a) : "l"(p));
    return a;
}
__device__ __forceinline__ void cp_async16(uint32_t dst, const void* src) {
    asm volatile("cp.async.cg.shared.global [%0], [%1], 16;" :: "r"(dst), "l"(src));
}
__device__ __forceinline__ void cp_commit() {
    asm volatile("cp.async.commit_group;" ::: "memory");
}
template <int N>
__device__ __forceinline__ void cp_wait() {
    asm volatile("cp.async.wait_group %0;" :: "n"(N) : "memory");
}
__device__ __forceinline__ void mma_f16(float d[4], const uint32_t a[4],
                                        uint32_t b0, uint32_t b1) {
    asm volatile(
        "mma.sync.aligned.m16n8k16.row.col.f32.f16.f16.f32 "
        "{%0,%1,%2,%3}, {%4,%5,%6,%7}, {%8,%9}, {%0,%1,%2,%3};"
        : "+f"(d[0]), "+f"(d[1]), "+f"(d[2]), "+f"(d[3])
        : "r"(a[0]), "r"(a[1]), "r"(a[2]), "r"(a[3]), "r"(b0), "r"(b1));
}
__device__ __forceinline__ uint32_t packh2(float lo, float hi) {
    __half2 h = __floats2half2_rn(lo, hi);
    return *(uint32_t*)&h;
}
__device__ __forceinline__ void ldm_x4t(uint32_t& r0, uint32_t& r1,
                                        uint32_t& r2, uint32_t& r3, uint32_t addr) {
    asm volatile("ldmatrix.sync.aligned.m8n8.x4.trans.shared.b16 {%0,%1,%2,%3}, [%4];"
                 : "=r"(r0), "=r"(r1), "=r"(r2), "=r"(r3) : "r"(addr));
}

// ================= x pre-pass: fp32 -> fp16 fragment-packed =================
// per (e, mtb, it): 32 frags (mt16 0..7 x s 0..3) x 32 lanes x uint4
__global__ void xpack_kernel(const float* __restrict__ x, uint4* __restrict__ xp)
{
    const int it = blockIdx.x, mt = blockIdx.y, e = blockIdx.z, tid = threadIdx.x;
    const float* src = x + ((long long)e * TOK_PER_E + mt * 128) * DIM + it * 64;
    uint4* dst = xp + ((long long)(e * 2 + mt) * 32 + it) * 1024;
#pragma unroll
    for (int j = 0; j < 4; j++) {
        int fl = tid + 256 * j;
        int fA = fl >> 5, lane = fl & 31;
        int mt16 = fA >> 2, s = fA & 3, g = lane >> 2, c = lane & 3;
        const float* p = src + (long long)(mt16 * 16 + g) * DIM + s * 16 + 2 * c;
        float2 q0 = *(const float2*)p;
        float2 q1 = *(const float2*)(p + 8 * DIM);
        float2 q2 = *(const float2*)(p + 8);
        float2 q3 = *(const float2*)(p + 8 * DIM + 8);
        uint4 v;
        v.x = packh2(q0.x, q0.y);
        v.y = packh2(q1.x, q1.y);
        v.z = packh2(q2.x, q2.y);
        v.w = packh2(q3.x, q3.y);
        dst[fl] = v;
    }
}

// ================= fused gate/up + SiLU =================
// BM=256, BN=64 per matrix, BK=64. 16 warps: wm(8) x wn(2), warp tile 32x32 per matrix.
__global__ __launch_bounds__(NTHREADS, 1)
void moe_gateup(const uint4* __restrict__ xp, const float* __restrict__ w1,
                const float* __restrict__ w3, uint4* __restrict__ hp)
{
    extern __shared__ char smem[];
    const int tid = threadIdx.x, lane = tid & 31, wid = tid >> 5;
    const int wm = wid >> 1, wn = wid & 1;
    const int e = blockIdx.z, nt = blockIdx.x;

    const uint4* xpe = xp + (long long)e * 65536;   // both 128-row blocks
    const float* w1e = w1 + (long long)e * DIM * HIDDEN + nt * 64;
    const float* w3e = w3 + (long long)e * DIM * HIDDEN + nt * 64;

    uint4 u1, u3;  // staged packed rows (1 per thread per matrix)

    auto ldgB = [&](int kt) {
        int k = tid >> 3, q = tid & 7;
        const float* p1 = w1e + (long long)(kt + k) * HIDDEN + q * 8;
        float4 x0 = *(const float4*)p1;
        float4 x1 = *(const float4*)(p1 + 4);
        u1.x = packh2(x0.x, x0.y); u1.y = packh2(x0.z, x0.w);
        u1.z = packh2(x1.x, x1.y); u1.w = packh2(x1.z, x1.w);
        const float* p3 = w3e + (long long)(kt + k) * HIDDEN + q * 8;
        float4 y0 = *(const float4*)p3;
        float4 y1 = *(const float4*)(p3 + 4);
        u3.x = packh2(y0.x, y0.y); u3.y = packh2(y0.z, y0.w);
        u3.z = packh2(y1.x, y1.y); u3.w = packh2(y1.z, y1.w);
    };
    auto stsB = [&](int buf) {
        char* b1 = smem + B_BASE + buf * 16384;
        int k = tid >> 3, q = tid & 7;
        uint32_t off = (uint32_t)k * 128 + ((q ^ (k & 7)) * 16);
        *(uint4*)(b1 + off) = u1;
        *(uint4*)(b1 + 8192 + off) = u3;
    };
    auto ldA = [&](int stage, int buf) {
        uint32_t sA = smem_u32(smem) + buf * A_PK;
#pragma unroll
        for (int j = 0; j < 4; j++) {
            int idx = tid + 512 * j;               // 0..2047
            int f = idx >> 5, ln = idx & 31;
            int mt16 = f >> 2, s = f & 3;
            const uint4* src = xpe + (long long)(mt16 >> 3) * 32768
                               + (long long)stage * 1024 + ((mt16 & 7) * 4 + s) * 32 + ln;
            cp_async16(sA + idx * 16, src);
        }
        cp_commit();
    };

    // ldmatrix lane bases
    const uint32_t kk0 = (lane & 7) + ((lane >> 3) & 1) * 8;
    uint32_t lmb[2];
#pragma unroll
    for (int q = 0; q < 2; q++) {
        uint32_t oct = (uint32_t)(wn * 4 + 2 * q) + (lane >> 4);
        lmb[q] = kk0 * 128 + ((oct ^ (kk0 & 7)) * 16);
    }

    float accG[2][4][4] = {}, accU[2][4][4] = {};

    ldgB(0);
    ldA(0, 0);
    stsB(0);
    ldgB(64);
    cp_wait<0>();
    __syncthreads();

    const int NIT = DIM / 64;  // 32
    for (int it = 0; it < NIT; ++it) {
        const int b = it & 1;
        if (it + 1 < NIT) ldA(it + 1, 1 - b);

        const uint4* Ap = (const uint4*)(smem + b * A_PK);
        const uint32_t Bb = smem_u32(smem) + B_BASE + b * 16384;

#pragma unroll
        for (int s = 0; s < 4; s++) {
            uint32_t a[2][4];
            {
                uint4 t0 = Ap[((2 * wm + 0) * 4 + s) * 32 + lane];
                uint4 t1 = Ap[((2 * wm + 1) * 4 + s) * 32 + lane];
                a[0][0] = t0.x; a[0][1] = t0.y; a[0][2] = t0.z; a[0][3] = t0.w;
                a[1][0] = t1.x; a[1][1] = t1.y; a[1][2] = t1.z; a[1][3] = t1.w;
            }
#pragma unroll
            for (int q = 0; q < 2; q++) {
                uint32_t addr = Bb + lmb[q] + (uint32_t)s * 2048;
                uint32_t r0, r1, r2, r3, c0, c1, c2, c3;
                ldm_x4t(r0, r1, r2, r3, addr);
                ldm_x4t(c0, c1, c2, c3, addr + 8192);
                mma_f16(accG[0][2 * q], a[0], r0, r1);
                mma_f16(accG[1][2 * q], a[1], r0, r1);
                mma_f16(accG[0][2 * q + 1], a[0], r2, r3);
                mma_f16(accG[1][2 * q + 1], a[1], r2, r3);
                mma_f16(accU[0][2 * q], a[0], c0, c1);
                mma_f16(accU[1][2 * q], a[1], c0, c1);
                mma_f16(accU[0][2 * q + 1], a[0], c2, c3);
                mma_f16(accU[1][2 * q + 1], a[1], c2, c3);
            }
        }
        if (it + 1 < NIT) { stsB(1 - b); ldgB((it + 2 < NIT) ? (it + 2) * 64 : 0); }
        cp_wait<0>();
        if (it + 1 < NIT) __syncthreads();
    }

    // epilogue: h = silu(gate)*up -> fp16 fragment-packed for down's A
    // hp per e: 16 stages x 64 frags (mt16*4+s) x 32 lanes x uint4
    uint4* hpe = hp + (long long)e * 32768 + nt * 2048;
#pragma unroll
    for (int mi = 0; mi < 2; mi++) {
#pragma unroll
        for (int nip = 0; nip < 2; nip++) {
            float hv[2][4];
#pragma unroll
            for (int q = 0; q < 2; q++) {
                int ni = 2 * nip + q;
#pragma unroll
                for (int j = 0; j < 4; j++) {
                    float gv = accG[mi][ni][j], uv = accU[mi][ni][j];
                    hv[q][j] = gv / (1.f + __expf(-gv)) * uv;
                }
            }
            uint4 v;
            v.x = packh2(hv[0][0], hv[0][1]);
            v.y = packh2(hv[0][2], hv[0][3]);
            v.z = packh2(hv[1][0], hv[1][1]);
            v.w = packh2(hv[1][2], hv[1][3]);
            int f = (wm * 2 + mi) * 4 + (wn * 2 + nip);
            hpe[f * 32 + lane] = v;
        }
    }
}

// ================= down-projection =================
// BM=256, BN=128, BK=64. 16 warps: wm(8) x wn(2), warp tile 32x64.
__global__ __launch_bounds__(NTHREADS, 1)
void moe_down(const uint4* __restrict__ hp, const float* __restrict__ w2,
              float* __restrict__ out)
{
    extern __shared__ char smem[];
    const int tid = threadIdx.x, lane = tid & 31, wid = tid >> 5;
    const int wm = wid >> 1, wn = wid & 1, g = lane >> 2, c = lane & 3;
    const int e = blockIdx.z, nt = blockIdx.x;

    const uint4* hpe = hp + (long long)e * 32768;
    const float* w2e = w2 + (long long)e * HIDDEN * DIM + nt * 128;

    uint4 u[2];

    auto ldgB = [&](int kt) {
#pragma unroll
        for (int j = 0; j < 2; j++) {
            int id = tid + 512 * j;
            int k = id >> 4, q = id & 15;
            const float* p = w2e + (long long)(kt + k) * DIM + q * 8;
            float4 x0 = *(const float4*)p;
            float4 x1 = *(const float4*)(p + 4);
            u[j].x = packh2(x0.x, x0.y); u[j].y = packh2(x0.z, x0.w);
            u[j].z = packh2(x1.x, x1.y); u[j].w = packh2(x1.z, x1.w);
        }
    };
    auto stsB = [&](int buf) {
        char* bb = smem + B_BASE + buf * 16384;
#pragma unroll
        for (int j = 0; j < 2; j++) {
            int id = tid + 512 * j;
            int k = id >> 4, q = id & 15;
            uint32_t off = (uint32_t)k * 256 + ((q ^ (k & 7)) * 16);
            *(uint4*)(bb + off) = u[j];
        }
    };
    auto ldA = [&](int stage, int buf) {
        uint32_t sA = smem_u32(smem) + buf * A_PK;
        const uint4* src = hpe + (long long)stage * 2048;
#pragma unroll
        for (int j = 0; j < 4; j++) {
            int idx = tid + 512 * j;
            cp_async16(sA + idx * 16, src + idx);
        }
        cp_commit();
    };

    const uint32_t kk0 = (lane & 7) + ((lane >> 3) & 1) * 8;
    uint32_t lmb[4];
#pragma unroll
    for (int q = 0; q < 4; q++) {
        uint32_t oct = (uint32_t)(wn * 8 + 2 * q) + (lane >> 4);
        lmb[q] = kk0 * 256 + ((oct ^ (kk0 & 7)) * 16);
    }

    float acc[2][8][4] = {};

    ldgB(0);
    ldA(0, 0);
    stsB(0);
    ldgB(64);
    cp_wait<0>();
    __syncthreads();

    const int NIT = HIDDEN / 64;  // 16
    for (int it = 0; it < NIT; ++it) {
        const int b = it & 1;
        if (it + 1 < NIT) ldA(it + 1, 1 - b);

        const uint4* Ap = (const uint4*)(smem + b * A_PK);
        const uint32_t Bb = smem_u32(smem) + B_BASE + b * 16384;

#pragma unroll
        for (int s = 0; s < 4; s++) {
            uint32_t a[2][4];
            {
                uint4 t0 = Ap[((2 * wm + 0) * 4 + s) * 32 + lane];
                uint4 t1 = Ap[((2 * wm + 1) * 4 + s) * 32 + lane];
                a[0][0] = t0.x; a[0][1] = t0.y; a[0][2] = t0.z; a[0][3] = t0.w;
                a[1][0] = t1.x; a[1][1] = t1.y; a[1][2] = t1.z; a[1][3] = t1.w;
            }
#pragma unroll
            for (int q = 0; q < 4; q++) {
                uint32_t r0, r1, r2, r3;
                ldm_x4t(r0, r1, r2, r3, Bb + lmb[q] + (uint32_t)s * 4096);
                mma_f16(acc[0][2 * q], a[0], r0, r1);
                mma_f16(acc[1][2 * q], a[1], r0, r1);
                mma_f16(acc[0][2 * q + 1], a[0], r2, r3);
                mma_f16(acc[1][2 * q + 1], a[1], r2, r3);
            }
        }
        if (it + 1 < NIT) { stsB(1 - b); ldgB((it + 2 < NIT) ? (it + 2) * 64 : 0); }
        cp_wait<0>();
        if (it + 1 < NIT) __syncthreads();
    }

    const int colbase = nt * 128 + wn * 64;
    const long long rowbase = (long long)e * TOK_PER_E + wm * 32;
#pragma unroll
    for (int mi = 0; mi < 2; mi++) {
        const long long r0 = rowbase + mi * 16 + g;
#pragma unroll
        for (int ni = 0; ni < 8; ni++) {
            const int col = colbase + ni * 8 + 2 * c;
            float* p0 = out + r0 * DIM + col;
            float* p1 = p0 + 8 * DIM;
            *(float2*)p0 = make_float2(acc[mi][ni][0], acc[mi][ni][1]);
            *(float2*)p1 = make_float2(acc[mi][ni][2], acc[mi][ni][3]);
        }
    }
}

// ================= launch =================
extern "C" void kernel_launch(void* const* d_in, const int* in_sizes, int n_in,
                              void* d_out, int out_size)
{
    const float* x  = (const float*)d_in[0];
    const float* w1 = (const float*)d_in[1];
    const float* w2 = (const float*)d_in[2];
    const float* w3 = (const float*)d_in[3];
    float* out = (float*)d_out;

    uint4* xp = nullptr;
    uint4* hp = nullptr;
    cudaGetSymbolAddress((void**)&xp, g_xp);
    cudaGetSymbolAddress((void**)&hp, g_hp);

    static bool attr_done = false;
    if (!attr_done) {
        cudaFuncSetAttribute(moe_gateup, cudaFuncAttributeMaxDynamicSharedMemorySize, SMEM_TOT);
        cudaFuncSetAttribute(moe_down, cudaFuncAttributeMaxDynamicSharedMemorySize, SMEM_TOT);
        attr_done = true;
    }

    {
        dim3 grid(DIM / 64, TOK_PER_E / 128, NUM_EXPERTS);   // (32, 2, 64)
        xpack_kernel<<<grid, 256>>>(x, xp);
    }
    {
        dim3 grid(HIDDEN / 64, 1, NUM_EXPERTS);              // (16, 1, 64)
        moe_gateup<<<grid, NTHREADS, SMEM_TOT>>>(xp, w1, w3, hp);
    }
    {
        dim3 grid(DIM / 128, 1, NUM_EXPERTS);                // (16, 1, 64)
        moe_down<<<grid, NTHREADS, SMEM_TOT>>>(hp, w2, out);
    }
}

// round 16
// speedup vs baseline: 1.1258x; 1.1258x over previous
#include <cuda_runtime.h>
#include <cuda_fp16.h>
#include <cstdint>

// ---------------- problem constants ----------------
#define NUM_EXPERTS 64
#define DIM 2048
#define HIDDEN 1024
#define TOK_PER_E 256
#define TOTAL_TOKENS (NUM_EXPERTS * TOK_PER_E)
#define NTHREADS 256

// scratch: fp16 fragment-packed x (64MB) and h (32MB)
__device__ uint4 g_xp[(size_t)TOTAL_TOKENS * DIM / 8];
__device__ uint4 g_hp[(size_t)TOTAL_TOKENS * HIDDEN / 8];

// ---------------- smem layout ----------------
// A stage: 16KB, 3-stage ring. B stage: 16KB, 2-stage.
#define A_PK 16384
#define B_BASE (3 * A_PK)                // 49152
#define SMEM_TOT (B_BASE + 2 * 16384)    // 81920

// ---------------- helpers ----------------
__device__ __forceinline__ uint32_t smem_u32(const void* p) {
    uint32_t a;
    asm("{ .reg .u64 t; cvta.to.shared.u64 t, %1; cvt.u32.u64 %0, t; }" : "=r"(a) : "l"(p));
    return a;
}
__device__ __forceinline__ void cp_async16(uint32_t dst, const void* src) {
    asm volatile("cp.async.cg.shared.global [%0], [%1], 16;" :: "r"(dst), "l"(src));
}
__device__ __forceinline__ void cp_commit() {
    asm volatile("cp.async.commit_group;" ::: "memory");
}
template <int N>
__device__ __forceinline__ void cp_wait() {
    asm volatile("cp.async.wait_group %0;" :: "n"(N) : "memory");
}
__device__ __forceinline__ void mma_f16(float d[4], const uint32_t a[4],
                                        uint32_t b0, uint32_t b1) {
    asm volatile(
        "mma.sync.aligned.m16n8k16.row.col.f32.f16.f16.f32 "
        "{%0,%1,%2,%3}, {%4,%5,%6,%7}, {%8,%9}, {%0,%1,%2,%3};"
        : "+f"(d[0]), "+f"(d[1]), "+f"(d[2]), "+f"(d[3])
        : "r"(a[0]), "r"(a[1]), "r"(a[2]), "r"(a[3]), "r"(b0), "r"(b1));
}
__device__ __forceinline__ uint32_t packh2(float lo, float hi) {
    __half2 h = __floats2half2_rn(lo, hi);
    return *(uint32_t*)&h;
}
__device__ __forceinline__ void ldm_x4t(uint32_t& r0, uint32_t& r1,
                                        uint32_t& r2, uint32_t& r3, uint32_t addr) {
    asm volatile("ldmatrix.sync.aligned.m8n8.x4.trans.shared.b16 {%0,%1,%2,%3}, [%4];"
                 : "=r"(r0), "=r"(r1), "=r"(r2), "=r"(r3) : "r"(addr));
}

// ================= x pre-pass: fp32 -> fp16 fragment-packed =================
__global__ void xpack_kernel(const float* __restrict__ x, uint4* __restrict__ xp)
{
    const int it = blockIdx.x, mt = blockIdx.y, e = blockIdx.z, tid = threadIdx.x;
    const float* src = x + ((long long)e * TOK_PER_E + mt * 128) * DIM + it * 64;
    uint4* dst = xp + ((long long)(e * 2 + mt) * 32 + it) * 1024;
#pragma unroll
    for (int j = 0; j < 4; j++) {
        int fl = tid + 256 * j;
        int fA = fl >> 5, lane = fl & 31;
        int mt16 = fA >> 2, s = fA & 3, g = lane >> 2, c = lane & 3;
        const float* p = src + (long long)(mt16 * 16 + g) * DIM + s * 16 + 2 * c;
        float2 q0 = *(const float2*)p;
        float2 q1 = *(const float2*)(p + 8 * DIM);
        float2 q2 = *(const float2*)(p + 8);
        float2 q3 = *(const float2*)(p + 8 * DIM + 8);
        uint4 v;
        v.x = packh2(q0.x, q0.y);
        v.y = packh2(q1.x, q1.y);
        v.z = packh2(q2.x, q2.y);
        v.w = packh2(q3.x, q3.y);
        dst[fl] = v;
    }
}

// ================= fused gate/up + SiLU =================
// BM=128, BN=64 per matrix, BK=64. 8 warps: wm(4) x wn(2), warp tile 32x32 per matrix.
// B smem: [k 0..63][n 0..63] fp16, 128B rows, chunk swizzle c^=(k&7).
// grid.x = nt*2 + mt so weight-sharing CTA pairs have adjacent bids.
__global__ __launch_bounds__(NTHREADS, 2)
void moe_gateup(const uint4* __restrict__ xp, const float* __restrict__ w1,
                const float* __restrict__ w3, uint4* __restrict__ hp)
{
    extern __shared__ char smem[];
    const int tid = threadIdx.x, lane = tid & 31, wid = tid >> 5;
    const int wm = wid >> 1, wn = wid & 1;
    const int e = blockIdx.z, mt = blockIdx.x & 1, nt = blockIdx.x >> 1;

    const uint4* xpe = xp + (long long)(e * 2 + mt) * 32 * 1024;
    const float* w1e = w1 + (long long)e * DIM * HIDDEN + nt * 64;
    const float* w3e = w3 + (long long)e * DIM * HIDDEN + nt * 64;

    uint4 u1[2], u3[2];  // staged packed rows

    auto ldgB = [&](int kt) {
#pragma unroll
        for (int j = 0; j < 2; j++) {
            int id = tid + 256 * j;
            int k = id >> 3, q = id & 7;
            const float* p1 = w1e + (long long)(kt + k) * HIDDEN + q * 8;
            float4 x0 = *(const float4*)p1;
            float4 x1 = *(const float4*)(p1 + 4);
            u1[j].x = packh2(x0.x, x0.y); u1[j].y = packh2(x0.z, x0.w);
            u1[j].z = packh2(x1.x, x1.y); u1[j].w = packh2(x1.z, x1.w);
            const float* p3 = w3e + (long long)(kt + k) * HIDDEN + q * 8;
            float4 y0 = *(const float4*)p3;
            float4 y1 = *(const float4*)(p3 + 4);
            u3[j].x = packh2(y0.x, y0.y); u3[j].y = packh2(y0.z, y0.w);
            u3[j].z = packh2(y1.x, y1.y); u3[j].w = packh2(y1.z, y1.w);
        }
    };
    auto stsB = [&](int buf) {
        char* b1 = smem + B_BASE + buf * 16384;
#pragma unroll
        for (int j = 0; j < 2; j++) {
            int id = tid + 256 * j;
            int k = id >> 3, q = id & 7;
            uint32_t off = (uint32_t)k * 128 + ((q ^ (k & 7)) * 16);
            *(uint4*)(b1 + off) = u1[j];
            *(uint4*)(b1 + 8192 + off) = u3[j];
        }
    };
    auto ldA = [&](int stage, int buf) {
        uint32_t sA = smem_u32(smem) + buf * A_PK;
        const uint4* src = xpe + (long long)stage * 1024;
#pragma unroll
        for (int j = 0; j < 4; j++) {
            int idx = tid + 256 * j;
            cp_async16(sA + idx * 16, src + idx);
        }
        cp_commit();
    };

    // ldmatrix lane bases (loop-invariant)
    const uint32_t kk0 = (lane & 7) + ((lane >> 3) & 1) * 8;
    uint32_t lmb[2];
#pragma unroll
    for (int q = 0; q < 2; q++) {
        uint32_t oct = (uint32_t)(wn * 4 + 2 * q) + (lane >> 4);
        lmb[q] = kk0 * 128 + ((oct ^ (kk0 & 7)) * 16);
    }

    float accG[2][4][4] = {}, accU[2][4][4] = {};

    ldgB(0);
    ldA(0, 0);
    ldA(1, 1);
    stsB(0);
    ldgB(64);
    cp_wait<1>();
    __syncthreads();

    const int NIT = DIM / 64;  // 32
    int a3 = 0, a3n = 2;
    for (int it = 0; it < NIT; ++it) {
        const int b = it & 1;
        if (it + 2 < NIT) ldA(it + 2, a3n);

        const uint4* Ap = (const uint4*)(smem + a3 * A_PK);
        const uint32_t Bb = smem_u32(smem) + B_BASE + b * 16384;

#pragma unroll
        for (int s = 0; s < 4; s++) {
            uint32_t a[2][4];
            {
                uint4 t0 = Ap[((2 * wm + 0) * 4 + s) * 32 + lane];
                uint4 t1 = Ap[((2 * wm + 1) * 4 + s) * 32 + lane];
                a[0][0] = t0.x; a[0][1] = t0.y; a[0][2] = t0.z; a[0][3] = t0.w;
                a[1][0] = t1.x; a[1][1] = t1.y; a[1][2] = t1.z; a[1][3] = t1.w;
            }
#pragma unroll
            for (int q = 0; q < 2; q++) {
                uint32_t addr = Bb + lmb[q] + (uint32_t)s * 2048;
                uint32_t r0, r1, r2, r3, c0, c1, c2, c3;
                ldm_x4t(r0, r1, r2, r3, addr);          // B1: frags 2q, 2q+1
                ldm_x4t(c0, c1, c2, c3, addr + 8192);   // B3
                mma_f16(accG[0][2 * q], a[0], r0, r1);
                mma_f16(accG[1][2 * q], a[1], r0, r1);
                mma_f16(accG[0][2 * q + 1], a[0], r2, r3);
                mma_f16(accG[1][2 * q + 1], a[1], r2, r3);
                mma_f16(accU[0][2 * q], a[0], c0, c1);
                mma_f16(accU[1][2 * q], a[1], c0, c1);
                mma_f16(accU[0][2 * q + 1], a[0], c2, c3);
                mma_f16(accU[1][2 * q + 1], a[1], c2, c3);
            }
        }
        if (it + 1 < NIT) stsB(1 - b);
        if (it + 2 < NIT) { ldgB((it + 2) * 64); cp_wait<1>(); }
        else cp_wait<0>();
        if (it + 1 < NIT) __syncthreads();
        a3 = (a3 == 2) ? 0 : a3 + 1;
        a3n = (a3n == 2) ? 0 : a3n + 1;
    }

    // epilogue: h = silu(gate)*up -> fp16, fragment-packed, coalesced uint4 stores
    uint4* hpe = hp + ((long long)(e * 2 + mt) * 16 + nt) * 1024;
#pragma unroll
    for (int mi = 0; mi < 2; mi++) {
#pragma unroll
        for (int nip = 0; nip < 2; nip++) {
            float hv[2][4];
#pragma unroll
            for (int q = 0; q < 2; q++) {
                int ni = 2 * nip + q;
#pragma unroll
                for (int j = 0; j < 4; j++) {
                    float gv = accG[mi][ni][j], uv = accU[mi][ni][j];
                    hv[q][j] = gv / (1.f + __expf(-gv)) * uv;
                }
            }
            uint4 v;
            v.x = packh2(hv[0][0], hv[0][1]);
            v.y = packh2(hv[0][2], hv[0][3]);
            v.z = packh2(hv[1][0], hv[1][1]);
            v.w = packh2(hv[1][2], hv[1][3]);
            int f_dn = (wm * 2 + mi) * 4 + (wn * 2 + nip);
            hpe[f_dn * 32 + lane] = v;
        }
    }
}

// ================= down-projection =================
// BM=128, BN=128, BK=64. Warp tile 32x64.
// B smem: [k 0..63][n 0..127] fp16, 256B rows, chunk swizzle c^=(k&7).
// grid.x = nt*2 + mt for adjacent weight-sharing pairs.
__global__ __launch_bounds__(NTHREADS, 2)
void moe_down(const uint4* __restrict__ hp, const float* __restrict__ w2,
              float* __restrict__ out)
{
    extern __shared__ char smem[];
    const int tid = threadIdx.x, lane = tid & 31, wid = tid >> 5;
    const int wm = wid >> 1, wn = wid & 1, g = lane >> 2, c = lane & 3;
    const int e = blockIdx.z, mt = blockIdx.x & 1, nt = blockIdx.x >> 1;

    const uint4* hpe = hp + (long long)(e * 2 + mt) * 16 * 1024;
    const float* w2e = w2 + (long long)e * HIDDEN * DIM + nt * 128;

    uint4 u[4];

    auto ldgB = [&](int kt) {
#pragma unroll
        for (int j = 0; j < 4; j++) {
            int id = tid + 256 * j;
            int k = id >> 4, q = id & 15;
            const float* p = w2e + (long long)(kt + k) * DIM + q * 8;
            float4 x0 = *(const float4*)p;
            float4 x1 = *(const float4*)(p + 4);
            u[j].x = packh2(x0.x, x0.y); u[j].y = packh2(x0.z, x0.w);
            u[j].z = packh2(x1.x, x1.y); u[j].w = packh2(x1.z, x1.w);
        }
    };
    auto stsB = [&](int buf) {
        char* bb = smem + B_BASE + buf * 16384;
#pragma unroll
        for (int j = 0; j < 4; j++) {
            int id = tid + 256 * j;
            int k = id >> 4, q = id & 15;
            uint32_t off = (uint32_t)k * 256 + ((q ^ (k & 7)) * 16);
            *(uint4*)(bb + off) = u[j];
        }
    };
    auto ldA = [&](int stage, int buf) {
        uint32_t sA = smem_u32(smem) + buf * A_PK;
        const uint4* src = hpe + (long long)stage * 1024;
#pragma unroll
        for (int j = 0; j < 4; j++) {
            int idx = tid + 256 * j;
            cp_async16(sA + idx * 16, src + idx);
        }
        cp_commit();
    };

    const uint32_t kk0 = (lane & 7) + ((lane >> 3) & 1) * 8;
    uint32_t lmb[4];
#pragma unroll
    for (int q = 0; q < 4; q++) {
        uint32_t oct = (uint32_t)(wn * 8 + 2 * q) + (lane >> 4);
        lmb[q] = kk0 * 256 + ((oct ^ (kk0 & 7)) * 16);
    }

    float acc[2][8][4] = {};

    ldgB(0);
    ldA(0, 0);
    ldA(1, 1);
    stsB(0);
    ldgB(64);
    cp_wait<1>();
    __syncthreads();

    const int NIT = HIDDEN / 64;  // 16
    int a3 = 0, a3n = 2;
    for (int it = 0; it < NIT; ++it) {
        const int b = it & 1;
        if (it + 2 < NIT) ldA(it + 2, a3n);

        const uint4* Ap = (const uint4*)(smem + a3 * A_PK);
        const uint32_t Bb = smem_u32(smem) + B_BASE + b * 16384;

#pragma unroll
        for (int s = 0; s < 4; s++) {
            uint32_t a[2][4];
            {
                uint4 t0 = Ap[((2 * wm + 0) * 4 + s) * 32 + lane];
                uint4 t1 = Ap[((2 * wm + 1) * 4 + s) * 32 + lane];
                a[0][0] = t0.x; a[0][1] = t0.y; a[0][2] = t0.z; a[0][3] = t0.w;
                a[1][0] = t1.x; a[1][1] = t1.y; a[1][2] = t1.z; a[1][3] = t1.w;
            }
#pragma unroll
            for (int q = 0; q < 4; q++) {
                uint32_t r0, r1, r2, r3;
                ldm_x4t(r0, r1, r2, r3, Bb + lmb[q] + (uint32_t)s * 4096);
                mma_f16(acc[0][2 * q], a[0], r0, r1);
                mma_f16(acc[1][2 * q], a[1], r0, r1);
                mma_f16(acc[0][2 * q + 1], a[0], r2, r3);
                mma_f16(acc[1][2 * q + 1], a[1], r2, r3);
            }
        }
        if (it + 1 < NIT) stsB(1 - b);
        if (it + 2 < NIT) { ldgB((it + 2) * 64); cp_wait<1>(); }
        else cp_wait<0>();
        if (it + 1 < NIT) __syncthreads();
        a3 = (a3 == 2) ? 0 : a3 + 1;
        a3n = (a3n == 2) ? 0 : a3n + 1;
    }

    const int colbase = nt * 128 + wn * 64;
    const long long rowbase = (long long)e * TOK_PER_E + mt * 128 + wm * 32;
#pragma unroll
    for (int mi = 0; mi < 2; mi++) {
        const long long r0 = rowbase + mi * 16 + g;
#pragma unroll
        for (int ni = 0; ni < 8; ni++) {
            const int col = colbase + ni * 8 + 2 * c;
            float* p0 = out + r0 * DIM + col;
            float* p1 = p0 + 8 * DIM;
            *(float2*)p0 = make_float2(acc[mi][ni][0], acc[mi][ni][1]);
            *(float2*)p1 = make_float2(acc[mi][ni][2], acc[mi][ni][3]);
        }
    }
}

// ================= launch =================
extern "C" void kernel_launch(void* const* d_in, const int* in_sizes, int n_in,
                              void* d_out, int out_size)
{
    const float* x  = (const float*)d_in[0];
    const float* w1 = (const float*)d_in[1];
    const float* w2 = (const float*)d_in[2];
    const float* w3 = (const float*)d_in[3];
    float* out = (float*)d_out;

    uint4* xp = nullptr;
    uint4* hp = nullptr;
    cudaGetSymbolAddress((void**)&xp, g_xp);
    cudaGetSymbolAddress((void**)&hp, g_hp);

    static bool attr_done = false;
    if (!attr_done) {
        cudaFuncSetAttribute(moe_gateup, cudaFuncAttributeMaxDynamicSharedMemorySize, SMEM_TOT);
        cudaFuncSetAttribute(moe_down, cudaFuncAttributeMaxDynamicSharedMemorySize, SMEM_TOT);
        attr_done = true;
    }

    {
        dim3 grid(DIM / 64, TOK_PER_E / 128, NUM_EXPERTS);   // (32, 2, 64)
        xpack_kernel<<<grid, 256>>>(x, xp);
    }
    {
        dim3 grid((HIDDEN / 64) * 2, 1, NUM_EXPERTS);        // (32, 1, 64)
        moe_gateup<<<grid, NTHREADS, SMEM_TOT>>>(xp, w1, w3, hp);
    }
    {
        dim3 grid((DIM / 128) * 2, 1, NUM_EXPERTS);          // (32, 1, 64)
        moe_down<<<grid, NTHREADS, SMEM_TOT>>>(hp, w2, out);
    }
}